// round 9
// baseline (speedup 1.0000x reference)
#include <cuda_runtime.h>
#include <cstdint>

// Problem constants
#define TT 512
#define BB 128
#define HH 1024
#define SIGMA_REC 0.15811388300841897f   // sqrt(2/0.2)*0.05

// Grid / tiling
#define NCTA 128          // 4 row-blocks x 32 col-blocks
#define NTHREADS 512      // 2 K-groups x 256 compute threads
#define CK 64             // K chunk staged in SMEM
#define NCHUNK (HH / CK)  // 16

// SMEM layout (floats)
#define ASTRIDE 132                 // 64 k-values duplicated (128) + 4 pad -> bank-safe, 16B-aligned rows
#define ABUF (32 * ASTRIDE)         // 4224 floats per A buffer
#define W_FLOATS (HH * 32)          // 32768
#define A_OFF W_FLOATS
#define WIH_OFF (A_OFF + 2 * ABUF)  // 41216
#define BIAS_OFF (WIH_OFF + 64)     // 41280
#define SMEM_FLOATS (BIAS_OFF + 32) // 41312
#define SMEM_BYTES (SMEM_FLOATS * 4) // 165248 B  (< 227 KB limit)

__device__ unsigned g_flags[NCTA];

__global__ void rnn_init_kernel() {
    if (threadIdx.x < NCTA) g_flags[threadIdx.x] = 0u;
}

__device__ __forceinline__ void st_rel(unsigned* p, unsigned v) {
    asm volatile("st.global.release.gpu.u32 [%0], %1;" :: "l"(p), "r"(v) : "memory");
}
__device__ __forceinline__ unsigned ld_acq(const unsigned* p) {
    unsigned v;
    asm volatile("ld.global.acquire.gpu.u32 %0, [%1];" : "=r"(v) : "l"(p) : "memory");
    return v;
}

// All-CTA barrier: per-CTA flag store (release) + every thread polls one flag (acquire).
// 128 CTAs, 1 CTA/SM (forced by 165KB smem), 148 SMs -> co-residency guaranteed.
__device__ __forceinline__ void grid_barrier(unsigned epoch) {
    __syncthreads();
    if (threadIdx.x == 0) st_rel(&g_flags[blockIdx.x], epoch);
    const unsigned idx = threadIdx.x & (NCTA - 1);
    while (ld_acq(&g_flags[idx]) < epoch) { }
    __syncthreads();
}

__global__ void __launch_bounds__(NTHREADS, 1)
rnn_persistent_kernel(const float* __restrict__ inp,
                      const float* __restrict__ init_state,
                      const float* __restrict__ noise,
                      const float* __restrict__ wih,
                      const float* __restrict__ whh,
                      const float* __restrict__ bias,
                      float* __restrict__ out)
{
    extern __shared__ float sm[];
    float* sW    = sm;              // [1024][32]  W_hh strip for this CTA's 32 cols
    float* sA    = sm + A_OFF;      // [2][32][132] relu(state) rows, duplicated pairs {a,a}
    float* sWih  = sm + WIH_OFF;    // [2][32]
    float* sBias = sm + BIAS_OFF;   // [32]
    float* sScr  = sm + A_OFF;      // reduction scratch (reuses A buf 0 after last chunk)

    const int tid  = threadIdx.x;
    const int cta  = blockIdx.x;
    const int row0 = (cta >> 5) * 32;   // batch-row block (4 blocks of 32)
    const int col0 = (cta & 31) * 32;   // hidden-col block (32 blocks of 32)

    // One-time: stage W strip into SMEM
    for (int idx = tid; idx < W_FLOATS; idx += NTHREADS) {
        const int k = idx >> 5, c = idx & 31;
        sW[idx] = whh[k * HH + col0 + c];
    }
    if (tid < 32) {
        sWih[tid]      = wih[col0 + tid];
        sWih[32 + tid] = wih[HH + col0 + tid];
        sBias[tid]     = bias[col0 + tid];
    }

    // K-split: group 0 = threads 0..255 (k 0..31 of each chunk),
    //          group 1 = threads 256..511 (k 32..63 of each chunk).
    const int group = tid >> 8;
    const int sub   = tid & 255;

    // Output mapping (per 256-thread group): warp footprint = 8 rows x 16 cols.
    const int wid    = sub >> 5;
    const int lane   = sub & 31;
    const int rowblk = wid & 3;     // 0..3  (8 rows each)
    const int colblk = wid >> 2;    // 0..1  (16 cols each)
    const int rl     = lane >> 2;   // 0..7
    const int cgl    = lane & 3;    // 0..3
    const int r      = rowblk * 8 + rl;       // local row 0..31
    const int cl     = colblk * 16 + cgl * 4; // local col, step 4
    const int grow   = row0 + r;
    const int gcol   = col0 + cl;

    // A-loader mapping: 512 threads stage one float4 each per chunk (32 rows x 16 quads)
    const int l_row = tid >> 4;          // 0..31
    const int l_kq  = tid & 15;          // 0..15

    // Write out[0] = initial_state (group 0 tile covers all 256 float4 of the tile)
    if (group == 0) {
        const float4 v = *(const float4*)&init_state[grow * HH + gcol];
        *(float4*)&out[grow * HH + gcol] = v;
    }
    grid_barrier(1u);

    #pragma unroll 1
    for (int t = 0; t < TT; ++t) {
        const float* Ot = out + (size_t)t * (BB * HH);
        float*       On = out + (size_t)(t + 1) * (BB * HH);

        // Prefetch epilogue operands early (group 0 only — it owns the epilogue)
        float4 nz; float2 iv; float4 old4;
        if (group == 0) {
            nz   = *(const float4*)&noise[((size_t)t * BB + grow) * HH + gcol];
            iv   = *(const float2*)&inp[((size_t)t * BB + grow) * 2];
            old4 = *(const float4*)&Ot[grow * HH + gcol];
        }

        // Load K-chunk 0: relu + duplicate into pairs {a,a} (one float4 per thread)
        {
            float4 v = *(const float4*)&Ot[(row0 + l_row) * HH + l_kq * 4];
            v.x = fmaxf(v.x, 0.f); v.y = fmaxf(v.y, 0.f); v.z = fmaxf(v.z, 0.f); v.w = fmaxf(v.w, 0.f);
            float* d = &sA[l_row * ASTRIDE + l_kq * 8];
            ((float4*)d)[0] = make_float4(v.x, v.x, v.y, v.y);
            ((float4*)d)[1] = make_float4(v.z, v.z, v.w, v.w);
        }
        __syncthreads();

        unsigned long long acc01 = 0ull, acc23 = 0ull;

        #pragma unroll 1
        for (int ck = 0; ck < NCHUNK; ++ck) {
            // Prefetch next chunk into registers (overlaps with compute below)
            float4 v;
            const int nb = (ck + 1) & 1;
            if (ck < NCHUNK - 1) {
                const int kb = (ck + 1) * CK;
                v = *(const float4*)&Ot[(row0 + l_row) * HH + kb + l_kq * 4];
            }

            // Inner product over this thread's K half of the chunk:
            // LDS.64 (dup a, 4-way bcast) + LDS.128 (4 W cols, 8-way bcast) + 2x fma.f32x2
            const float* aRow = &sA[(ck & 1) * ABUF + r * ASTRIDE + group * 64];
            const float* wPtr = &sW[(ck * CK + group * 32) * 32 + cl];
            #pragma unroll
            for (int kk = 0; kk < 32; ++kk) {
                const unsigned long long a2 = *(const unsigned long long*)(aRow + 2 * kk);
                const ulonglong2 w = *(const ulonglong2*)(wPtr + kk * 32);
                asm("fma.rn.f32x2 %0, %1, %2, %0;" : "+l"(acc01) : "l"(a2), "l"(w.x));
                asm("fma.rn.f32x2 %0, %1, %2, %0;" : "+l"(acc23) : "l"(a2), "l"(w.y));
            }

            if (ck < NCHUNK - 1) {
                v.x = fmaxf(v.x, 0.f); v.y = fmaxf(v.y, 0.f); v.z = fmaxf(v.z, 0.f); v.w = fmaxf(v.w, 0.f);
                float* d = &sA[nb * ABUF + l_row * ASTRIDE + l_kq * 8];
                ((float4*)d)[0] = make_float4(v.x, v.x, v.y, v.y);
                ((float4*)d)[1] = make_float4(v.z, v.z, v.w, v.w);
                __syncthreads();
            }
        }

        // Unpack accumulators
        float c0, c1, c2, c3;
        {
            unsigned u0, u1, u2, u3;
            asm("mov.b64 {%0, %1}, %2;" : "=r"(u0), "=r"(u1) : "l"(acc01));
            asm("mov.b64 {%0, %1}, %2;" : "=r"(u2), "=r"(u3) : "l"(acc23));
            c0 = __uint_as_float(u0); c1 = __uint_as_float(u1);
            c2 = __uint_as_float(u2); c3 = __uint_as_float(u3);
        }

        // Cross-group reduction: group 1 dumps partials into scratch (A buf 0 region,
        // free now: last chunk read buf 1, and buf 0 readers synced at end of ck=14).
        if (group == 1) {
            *(float4*)&sScr[sub * 4] = make_float4(c0, c1, c2, c3);
        }
        __syncthreads();

        if (group == 0) {
            const float4 p = *(const float4*)&sScr[sub * 4];
            c0 += p.x; c1 += p.y; c2 += p.z; c3 += p.w;

            // Epilogue: drive = inp@Wih + bias + noise*SIGMA; state = 0.8*old + 0.2*(mat + drive)
            const float wa0 = sWih[cl],      wa1 = sWih[cl + 1],      wa2 = sWih[cl + 2],      wa3 = sWih[cl + 3];
            const float wb0 = sWih[32 + cl], wb1 = sWih[32 + cl + 1], wb2 = sWih[32 + cl + 2], wb3 = sWih[32 + cl + 3];
            const float b0  = sBias[cl],     b1  = sBias[cl + 1],     b2  = sBias[cl + 2],     b3  = sBias[cl + 3];

            float4 res;
            res.x = 0.8f * old4.x + 0.2f * (c0 + iv.x * wa0 + iv.y * wb0 + b0 + SIGMA_REC * nz.x);
            res.y = 0.8f * old4.y + 0.2f * (c1 + iv.x * wa1 + iv.y * wb1 + b1 + SIGMA_REC * nz.y);
            res.z = 0.8f * old4.z + 0.2f * (c2 + iv.x * wa2 + iv.y * wb2 + b2 + SIGMA_REC * nz.z);
            res.w = 0.8f * old4.w + 0.2f * (c3 + iv.x * wa3 + iv.y * wb3 + b3 + SIGMA_REC * nz.w);
            *(float4*)&On[grow * HH + gcol] = res;
        }

        // grid_barrier's leading __syncthreads also fences scratch reads before
        // next step's chunk-0 staging overwrites the scratch region.
        grid_barrier((unsigned)(t + 2));
    }
}

extern "C" void kernel_launch(void* const* d_in, const int* in_sizes, int n_in,
                              void* d_out, int out_size) {
    const float* inp   = (const float*)d_in[0];  // [512,128,2]
    const float* inis  = (const float*)d_in[1];  // [128,1024]
    const float* noise = (const float*)d_in[2];  // [512,128,1024]
    const float* wih   = (const float*)d_in[3];  // [2,1024]
    const float* whh   = (const float*)d_in[4];  // [1024,1024]
    const float* bias  = (const float*)d_in[5];  // [1,1024]
    float* out = (float*)d_out;                  // [513,128,1024]

    cudaFuncSetAttribute(rnn_persistent_kernel,
                         cudaFuncAttributeMaxDynamicSharedMemorySize, SMEM_BYTES);

    rnn_init_kernel<<<1, 128>>>();
    rnn_persistent_kernel<<<NCTA, NTHREADS, SMEM_BYTES>>>(inp, inis, noise, wih, whh, bias, out);
}

// round 10
// speedup vs baseline: 1.6522x; 1.6522x over previous
#include <cuda_runtime.h>
#include <cstdint>

// Problem constants
#define TT 512
#define BB 128
#define HH 1024
#define SIGMA_REC 0.15811388300841897f   // sqrt(2/0.2)*0.05

// Grid / threads
#define NCTA 128          // 4 row-blocks x 32 col-blocks
#define NTHREADS 512      // 8 k-split groups x 64 threads
#define NGROUP 8
#define CK 64             // k per staged chunk
#define NCHUNK (HH / CK)  // 16
#define PAIRS_PER_CHUNK 32
#define PAIRS_PER_GROUP 4 // pairs per group per chunk

// SMEM layout (floats)
#define ASTRIDE 68                   // 64 k + 4 pad: conflict-free & 16B-aligned rows
#define ABUF (32 * ASTRIDE)          // 2176
#define W_FLOATS (HH * 32)           // 32768, k-pair-interleaved: idx=(k>>1)*64 + c*2 + (k&1)
#define A_OFF W_FLOATS
#define SCR_OFF (A_OFF + 2 * ABUF)   // 37120
#define SCR_STRIDE 20                // 16 floats + 4 pad per thread-slot
#define SCR_GROUP (64 * SCR_STRIDE)  // 1280
#define WIH_OFF (SCR_OFF + 7 * SCR_GROUP)   // 46080
#define BIAS_OFF (WIH_OFF + 64)
#define SMEM_FLOATS (BIAS_OFF + 32)         // 46176
#define SMEM_BYTES (SMEM_FLOATS * 4)        // 184704 B (< 227 KB)

#define FMA2(acc, a, w) asm("fma.rn.f32x2 %0, %1, %2, %0;" : "+l"(acc) : "l"(a), "l"(w))

__device__ unsigned g_flags[NCTA];

__global__ void rnn_init_kernel() {
    if (threadIdx.x < NCTA) g_flags[threadIdx.x] = 0u;
}

__device__ __forceinline__ void st_rel(unsigned* p, unsigned v) {
    asm volatile("st.global.release.gpu.u32 [%0], %1;" :: "l"(p), "r"(v) : "memory");
}
__device__ __forceinline__ unsigned ld_acq(const unsigned* p) {
    unsigned v;
    asm volatile("ld.global.acquire.gpu.u32 %0, [%1];" : "=r"(v) : "l"(p) : "memory");
    return v;
}

// All-CTA barrier (proven in R8/R9): per-CTA release flag + all threads poll.
__device__ __forceinline__ void grid_barrier(unsigned epoch) {
    __syncthreads();
    if (threadIdx.x == 0) st_rel(&g_flags[blockIdx.x], epoch);
    const unsigned idx = threadIdx.x & (NCTA - 1);
    while (ld_acq(&g_flags[idx]) < epoch) { }
    __syncthreads();
}

__global__ void __launch_bounds__(NTHREADS, 1)
rnn_persistent_kernel(const float* __restrict__ inp,
                      const float* __restrict__ init_state,
                      const float* __restrict__ noise,
                      const float* __restrict__ wih,
                      const float* __restrict__ whh,
                      const float* __restrict__ bias,
                      float* __restrict__ out)
{
    extern __shared__ float sm[];
    float* sW    = sm;              // [512 j][32 c][2 parity]  W_hh k-pair-interleaved
    float* sA    = sm + A_OFF;      // [2][32 r][68]  relu(state), plain (no dup)
    float* sScr  = sm + SCR_OFF;    // [7 g][64 s][20] partial tiles
    float* sWih  = sm + WIH_OFF;    // [2][32]
    float* sBias = sm + BIAS_OFF;   // [32]

    const int tid  = threadIdx.x;
    const int cta  = blockIdx.x;
    const int row0 = (cta >> 5) * 32;   // batch-row block
    const int col0 = (cta & 31) * 32;   // hidden-col block

    // One-time: stage W strip k-pair-interleaved
    for (int idx = tid; idx < W_FLOATS; idx += NTHREADS) {
        const int k = idx >> 5, c = idx & 31;
        sW[(k >> 1) * 64 + c * 2 + (k & 1)] = whh[k * HH + col0 + c];
    }
    if (tid < 32) {
        sWih[tid]      = wih[col0 + tid];
        sWih[32 + tid] = wih[HH + col0 + tid];
        sBias[tid]     = bias[col0 + tid];
    }

    // K-split groups: group g handles pairs [g*4, g*4+4) of every 32-pair chunk.
    const int group = tid >> 6;         // 0..7
    const int s     = tid & 63;
    const int cql   = s >> 3;           // 0..7 -> cols cql*4 .. +3
    const int rql   = s & 7;            // rows {rql, rql+8, rql+16, rql+24}
    const int clo   = cql * 4;

    // Staging mapping: 512 threads store one relu'd float4 (32 rows x 16 quads)
    const int l_r = tid >> 4;           // 0..31
    const int l_q = tid & 15;           // 0..15

    // out[0] = initial_state (256 threads cover the 32x32 tile)
    if (tid < 256) {
        const int r = tid >> 3, c4 = (tid & 7) * 4;
        const float4 v = *(const float4*)&init_state[(row0 + r) * HH + col0 + c4];
        *(float4*)&out[(row0 + r) * HH + col0 + c4] = v;
    }
    grid_barrier(1u);

    #pragma unroll 1
    for (int t = 0; t < TT; ++t) {
        const float* Ot = out + (size_t)t * (BB * HH);
        float*       On = out + (size_t)(t + 1) * (BB * HH);

        // Stage chunk 0
        {
            float4 v = *(const float4*)&Ot[(row0 + l_r) * HH + l_q * 4];
            v.x = fmaxf(v.x, 0.f); v.y = fmaxf(v.y, 0.f); v.z = fmaxf(v.z, 0.f); v.w = fmaxf(v.w, 0.f);
            *(float4*)&sA[l_r * ASTRIDE + l_q * 4] = v;
        }
        __syncthreads();

        unsigned long long acc[4][4];
        #pragma unroll
        for (int i = 0; i < 4; ++i)
            #pragma unroll
            for (int j = 0; j < 4; ++j) acc[i][j] = 0ull;

        #pragma unroll 1
        for (int ck = 0; ck < NCHUNK; ++ck) {
            // Prefetch next chunk
            float4 v;
            const int nb = (ck + 1) & 1;
            if (ck < NCHUNK - 1) {
                v = *(const float4*)&Ot[(row0 + l_r) * HH + (ck + 1) * CK + l_q * 4];
            }

            const float* aB = &sA[(ck & 1) * ABUF];
            const int jloc  = group * PAIRS_PER_GROUP;           // pair idx within chunk
            const int jglob = ck * PAIRS_PER_CHUNK + jloc;       // global pair idx
            #pragma unroll
            for (int jj = 0; jj < PAIRS_PER_GROUP; ++jj) {
                const int jo2 = (jloc + jj) * 2;
                // a pairs (k even, k odd) for 4 strided rows — no duplication
                const unsigned long long a0 = *(const unsigned long long*)(aB + (rql +  0) * ASTRIDE + jo2);
                const unsigned long long a1 = *(const unsigned long long*)(aB + (rql +  8) * ASTRIDE + jo2);
                const unsigned long long a2 = *(const unsigned long long*)(aB + (rql + 16) * ASTRIDE + jo2);
                const unsigned long long a3 = *(const unsigned long long*)(aB + (rql + 24) * ASTRIDE + jo2);
                // W k-pairs for 4 cols
                const float* wj = sW + (size_t)(jglob + jj) * 64 + cql * 8;
                const ulonglong2 w01 = *(const ulonglong2*)(wj);
                const ulonglong2 w23 = *(const ulonglong2*)(wj + 4);
                FMA2(acc[0][0], a0, w01.x); FMA2(acc[0][1], a0, w01.y);
                FMA2(acc[0][2], a0, w23.x); FMA2(acc[0][3], a0, w23.y);
                FMA2(acc[1][0], a1, w01.x); FMA2(acc[1][1], a1, w01.y);
                FMA2(acc[1][2], a1, w23.x); FMA2(acc[1][3], a1, w23.y);
                FMA2(acc[2][0], a2, w01.x); FMA2(acc[2][1], a2, w01.y);
                FMA2(acc[2][2], a2, w23.x); FMA2(acc[2][3], a2, w23.y);
                FMA2(acc[3][0], a3, w01.x); FMA2(acc[3][1], a3, w01.y);
                FMA2(acc[3][2], a3, w23.x); FMA2(acc[3][3], a3, w23.y);
            }

            if (ck < NCHUNK - 1) {
                v.x = fmaxf(v.x, 0.f); v.y = fmaxf(v.y, 0.f); v.z = fmaxf(v.z, 0.f); v.w = fmaxf(v.w, 0.f);
                *(float4*)&sA[nb * ABUF + l_r * ASTRIDE + l_q * 4] = v;
                __syncthreads();
            }
        }

        // Pair-sum: even-k + odd-k partials
        float c_[4][4];
        #pragma unroll
        for (int i = 0; i < 4; ++i)
            #pragma unroll
            for (int j = 0; j < 4; ++j) {
                unsigned lo, hi;
                asm("mov.b64 {%0, %1}, %2;" : "=r"(lo), "=r"(hi) : "l"(acc[i][j]));
                c_[i][j] = __uint_as_float(lo) + __uint_as_float(hi);
            }

        // Groups 1-7: store partial tiles. Group 0: prefetch epilogue operands
        // (LDG latency overlapped with the stores + barrier).
        float4 old4[4], nz4[4]; float2 iv2[4];
        if (group != 0) {
            float* dst = &sScr[(group - 1) * SCR_GROUP + s * SCR_STRIDE];
            #pragma unroll
            for (int i = 0; i < 4; ++i)
                *(float4*)(dst + i * 4) = make_float4(c_[i][0], c_[i][1], c_[i][2], c_[i][3]);
        } else {
            #pragma unroll
            for (int i = 0; i < 4; ++i) {
                const int gr = row0 + rql + 8 * i;
                old4[i] = *(const float4*)&Ot[gr * HH + col0 + clo];
                nz4[i]  = *(const float4*)&noise[((size_t)t * BB + gr) * HH + col0 + clo];
                iv2[i]  = *(const float2*)&inp[((size_t)t * BB + gr) * 2];
            }
        }
        __syncthreads();

        if (group == 0) {
            // Reduce the 7 partial tiles
            #pragma unroll 1
            for (int g = 1; g < NGROUP; ++g) {
                const float* src = &sScr[(g - 1) * SCR_GROUP + s * SCR_STRIDE];
                #pragma unroll
                for (int i = 0; i < 4; ++i) {
                    const float4 p = *(const float4*)(src + i * 4);
                    c_[i][0] += p.x; c_[i][1] += p.y; c_[i][2] += p.z; c_[i][3] += p.w;
                }
            }

            const float wa0 = sWih[clo],      wa1 = sWih[clo + 1],      wa2 = sWih[clo + 2],      wa3 = sWih[clo + 3];
            const float wb0 = sWih[32 + clo], wb1 = sWih[32 + clo + 1], wb2 = sWih[32 + clo + 2], wb3 = sWih[32 + clo + 3];
            const float b0  = sBias[clo],     b1  = sBias[clo + 1],     b2  = sBias[clo + 2],     b3  = sBias[clo + 3];

            #pragma unroll
            for (int i = 0; i < 4; ++i) {
                const int gr = row0 + rql + 8 * i;
                float4 res;
                res.x = 0.8f * old4[i].x + 0.2f * (c_[i][0] + iv2[i].x * wa0 + iv2[i].y * wb0 + b0 + SIGMA_REC * nz4[i].x);
                res.y = 0.8f * old4[i].y + 0.2f * (c_[i][1] + iv2[i].x * wa1 + iv2[i].y * wb1 + b1 + SIGMA_REC * nz4[i].y);
                res.z = 0.8f * old4[i].z + 0.2f * (c_[i][2] + iv2[i].x * wa2 + iv2[i].y * wb2 + b2 + SIGMA_REC * nz4[i].z);
                res.w = 0.8f * old4[i].w + 0.2f * (c_[i][3] + iv2[i].x * wa3 + iv2[i].y * wb3 + b3 + SIGMA_REC * nz4[i].w);
                *(float4*)&On[gr * HH + col0 + clo] = res;
            }
        }

        grid_barrier((unsigned)(t + 2));
    }
}

extern "C" void kernel_launch(void* const* d_in, const int* in_sizes, int n_in,
                              void* d_out, int out_size) {
    const float* inp   = (const float*)d_in[0];  // [512,128,2]
    const float* inis  = (const float*)d_in[1];  // [128,1024]
    const float* noise = (const float*)d_in[2];  // [512,128,1024]
    const float* wih   = (const float*)d_in[3];  // [2,1024]
    const float* whh   = (const float*)d_in[4];  // [1024,1024]
    const float* bias  = (const float*)d_in[5];  // [1,1024]
    float* out = (float*)d_out;                  // [513,128,1024]

    cudaFuncSetAttribute(rnn_persistent_kernel,
                         cudaFuncAttributeMaxDynamicSharedMemorySize, SMEM_BYTES);

    rnn_init_kernel<<<1, 128>>>();
    rnn_persistent_kernel<<<NCTA, NTHREADS, SMEM_BYTES>>>(inp, inis, noise, wih, whh, bias, out);
}